// round 12
// baseline (speedup 1.0000x reference)
#include <cuda_runtime.h>
#include <cstdint>

// ============================================================================
// Problem constants
// ============================================================================
#define K_DIM 12288
#define M_DIM 8192
#define C_DIM 1000
#define N_PAD 1024

// GEMM tiling (int8 TN: A[M,K] row-major, B[N,K] row-major = "col" operand)
#define BM 128
#define BN 128
#define BK 128                      // bytes of K per chunk
#define CPT 96                      // chunks per tile (K_DIM / BK)
#define NTILES 512                  // (M/BM) * (N_PAD/BN) = 64*8
#define TOTAL_UNITS (NTILES * CPT)  // 49152 chunk-units
#define NCTA 296                    // 148 SMs * occ 2 -> single balanced wave
#define UNITS_BASE (TOTAL_UNITS / NCTA)               // 166
#define UNITS_REM  (TOTAL_UNITS - NCTA * UNITS_BASE)  // 16

#define STAGES 3
#define A_ST (BM * BK)              // 16384 B
#define B_ST (BN * BK)              // 16384 B
#define STG_BYTES (A_ST + B_ST)     // 32768 B
#define SMEM_BYTES (STAGES * STG_BYTES)  // 98304 B

// conv grid split
#define A_BLOCKS 24576              // (M*K/16)/256
#define W_BLOCKS 3072               // (N_PAD*K/16)/256

// ============================================================================
// Device scratch (allocation-free: __device__ globals)
// ============================================================================
__device__ int8_t g_A8[(size_t)M_DIM * K_DIM];   // sign(input)  as s8
__device__ int8_t g_W8[(size_t)N_PAD * K_DIM];   // sign(weight) as s8, zero-pad

// ============================================================================
// PTX helpers
// ============================================================================
__device__ __forceinline__ void cp16(uint32_t dst, const void* src) {
    asm volatile("cp.async.cg.shared.global [%0], [%1], 16;"
                 :: "r"(dst), "l"(src));
}
__device__ __forceinline__ void cp_commit() {
    asm volatile("cp.async.commit_group;");
}
__device__ __forceinline__ void cp_wait1() {
    asm volatile("cp.async.wait_group 1;");
}

__device__ __forceinline__ void ldsm_x4(uint32_t& r0, uint32_t& r1,
                                        uint32_t& r2, uint32_t& r3,
                                        uint32_t addr) {
    asm volatile("ldmatrix.sync.aligned.m8n8.x4.shared.b16 {%0,%1,%2,%3}, [%4];"
                 : "=r"(r0), "=r"(r1), "=r"(r2), "=r"(r3) : "r"(addr));
}

__device__ __forceinline__ void imma16832(int* c, const uint32_t* a,
                                          uint32_t b0, uint32_t b1) {
    asm volatile(
        "mma.sync.aligned.m16n8k32.row.col.s32.s8.s8.s32 "
        "{%0,%1,%2,%3}, {%4,%5,%6,%7}, {%8,%9}, {%0,%1,%2,%3};"
        : "+r"(c[0]), "+r"(c[1]), "+r"(c[2]), "+r"(c[3])
        : "r"(a[0]), "r"(a[1]), "r"(a[2]), "r"(a[3]), "r"(b0), "r"(b1));
}

__device__ __forceinline__ int8_t sgn8(float x) {
    return (int8_t)((x > 0.f) - (x < 0.f));
}
__device__ __forceinline__ uint32_t pack4(float4 f) {
    uint32_t a = (uint8_t)sgn8(f.x), b = (uint8_t)sgn8(f.y);
    uint32_t c = (uint8_t)sgn8(f.z), d = (uint8_t)sgn8(f.w);
    return a | (b << 8) | (c << 16) | (d << 24);
}

// ============================================================================
// Kernel 1: fused sign-quantize fp32 -> s8 for A and W (16 elems/thread)
// ============================================================================
__global__ void conv_kernel(const float4* __restrict__ in,
                            const float4* __restrict__ w) {
    size_t b = blockIdx.x;
    if (b < A_BLOCKS) {
        size_t t = b * 256 + threadIdx.x;
        const float4* p = in + t * 4;
        uint4 o;
        o.x = pack4(p[0]); o.y = pack4(p[1]);
        o.z = pack4(p[2]); o.w = pack4(p[3]);
        reinterpret_cast<uint4*>(g_A8)[t] = o;
    } else {
        size_t t = (b - A_BLOCKS) * 256 + threadIdx.x;
        uint4 o = make_uint4(0u, 0u, 0u, 0u);
        if (t * 16 < (size_t)C_DIM * K_DIM) {   // rows >= 1000 stay zero
            const float4* p = w + t * 4;
            o.x = pack4(p[0]); o.y = pack4(p[1]);
            o.z = pack4(p[2]); o.w = pack4(p[3]);
        }
        reinterpret_cast<uint4*>(g_W8)[t] = o;
    }
}

// ============================================================================
// Chunk compute helper: 4 k-steps, 4 m-tiles, NTL n-tiles per warp.
// NTL=4 is the full path; NTL=1 is the (tn==7, wn==3) padded-column path.
// ============================================================================
template <int NTL>
__device__ __forceinline__ void compute_chunk(
    uint32_t sa, uint32_t sB, int acc[4][4][4],
    uint32_t a_r0off, uint32_t axc, uint32_t b_r0off, uint32_t bxc) {
#pragma unroll
    for (int ks = 0; ks < 4; ks++) {
        const uint32_t kc = ks * 32;
        uint32_t bf[4][2];
#pragma unroll
        for (int p = 0; p < (NTL > 2 ? 2 : 1); p++) {
            uint32_t addr = sB + b_r0off + p * 2048 + (kc ^ bxc);
            ldsm_x4(bf[2 * p][0], bf[2 * p][1],
                    bf[2 * p + 1][0], bf[2 * p + 1][1], addr);
        }
#pragma unroll
        for (int mt = 0; mt < 4; mt++) {
            uint32_t af[4];
            uint32_t addr = sa + a_r0off + mt * 2048 + (kc ^ axc);
            ldsm_x4(af[0], af[1], af[2], af[3], addr);
#pragma unroll
            for (int nt = 0; nt < NTL; nt++)
                imma16832(acc[mt][nt], af, bf[nt][0], bf[nt][1]);
        }
    }
}

// ============================================================================
// Kernel 2: int8 IMMA GEMM, balanced continuous chunk stream.
// 296 CTAs each own a contiguous range of chunk-units (tile*96 + kchunk).
// The cp.async pipeline runs continuously across tile boundaries (no
// drain/refill); one __syncthreads per chunk; atomic fp32 epilogue per tile
// segment (exact: integer-valued, |v| <= 12288).
// ============================================================================
__global__ void __launch_bounds__(256, 2)
bgemm_kernel(float* __restrict__ out) {
    extern __shared__ char smem[];
    const uint32_t sb = (uint32_t)__cvta_generic_to_shared(smem);

    const int tid = threadIdx.x;
    const int lane = tid & 31;
    const int wid = tid >> 5;
    const int wm = wid & 1;        // 2 warp rows   (64 m each)
    const int wn = wid >> 1;       // 4 warp cols   (32 n each)

    // ---- g2s copy offsets, base forms (j-th copy adds j*4096 / j*32*K_DIM) ----
    const uint32_t row0 = tid >> 3;
    const uint32_t col0 = (tid & 7u) * 16u;
    const uint32_t dst0 = row0 * BK + (col0 ^ ((row0 & 7u) * 16u));
    const uint32_t src0 = row0 * K_DIM + col0;

    // ---- ldmatrix address components ----
    const uint32_t lswz = (lane & 7u) * 16u;
    const uint32_t a_r0off = (uint32_t)(wm * 64 + (lane & 15)) * BK;
    const uint32_t axc = (((lane >> 4) & 1u) * 16u) ^ lswz;
    const uint32_t b_r0off =
        (uint32_t)(wn * 32 + ((lane >> 4) & 1) * 8 + (lane & 7)) * BK;
    const uint32_t bxc = (((lane >> 3) & 1u) * 16u) ^ lswz;

    // ---- balanced work range ----
    const int bid = blockIdx.x;
    const int u0 = bid * UNITS_BASE + min(bid, UNITS_REM);
    const int n_units = UNITS_BASE + (bid < UNITS_REM ? 1 : 0);

    // ---- stream cursors ----
    int t_cur = u0 / CPT;
    int c_cur = u0 - t_cur * CPT;

    int acc[4][4][4];
#pragma unroll
    for (int i = 0; i < 4; i++)
#pragma unroll
        for (int j = 0; j < 4; j++)
#pragma unroll
            for (int r = 0; r < 4; r++) acc[i][j][r] = 0;

    // ---- prologue: prefetch units u0, u0+1 into stages 0,1 ----
    int tp = t_cur, cp_ = c_cur;
#pragma unroll
    for (int s = 0; s < 2; s++) {
        uint32_t base = sb + s * STG_BYTES;
        uint32_t offA = (uint32_t)(tp >> 3) * (BM * K_DIM) + (uint32_t)cp_ * BK;
        uint32_t offW = (uint32_t)(tp & 7) * (BN * K_DIM) + (uint32_t)cp_ * BK;
#pragma unroll
        for (int j = 0; j < 4; j++)
            cp16(base + dst0 + j * 4096, g_A8 + offA + src0 + j * (32 * K_DIM));
#pragma unroll
        for (int j = 0; j < 4; j++)
            cp16(base + A_ST + dst0 + j * 4096,
                 g_W8 + offW + src0 + j * (32 * K_DIM));
        cp_commit();
        if (++cp_ == CPT) { cp_ = 0; ++tp; }
    }
    // (tp, cp_) now points at unit u0+2 (prefetch cursor)

    int st_cur = 0, st_pre = 2;

    for (int i = 0; i < n_units; i++) {
        cp_wait1();          // unit i's group arrived (<=1 pending: unit i+1)
        __syncthreads();     // collectivize; all threads done computing i-1

        // ---- prefetch unit u0+i+2 into stage st_pre ----
        if (i + 2 < n_units) {
            uint32_t base = sb + st_pre * STG_BYTES;
            uint32_t offA =
                (uint32_t)(tp >> 3) * (BM * K_DIM) + (uint32_t)cp_ * BK;
            uint32_t offW =
                (uint32_t)(tp & 7) * (BN * K_DIM) + (uint32_t)cp_ * BK;
#pragma unroll
            for (int j = 0; j < 4; j++)
                cp16(base + dst0 + j * 4096,
                     g_A8 + offA + src0 + j * (32 * K_DIM));
#pragma unroll
            for (int j = 0; j < 4; j++)
                cp16(base + A_ST + dst0 + j * 4096,
                     g_W8 + offW + src0 + j * (32 * K_DIM));
            if (++cp_ == CPT) { cp_ = 0; ++tp; }
        }
        cp_commit();
        if (++st_pre == STAGES) st_pre = 0;

        // ---- compute current chunk from stage st_cur ----
        {
            uint32_t sa = sb + st_cur * STG_BYTES;
            uint32_t sB = sa + A_ST;
            if (((t_cur & 7) == 7) && (wn == 3))
                compute_chunk<1>(sa, sB, acc, a_r0off, axc, b_r0off, bxc);
            else
                compute_chunk<4>(sa, sB, acc, a_r0off, axc, b_r0off, bxc);
        }
        if (++st_cur == STAGES) st_cur = 0;

        // ---- advance & segment epilogue (overlaps in-flight cp.async) ----
        ++c_cur;
        if (c_cur == CPT || i == n_units - 1) {
            const int rbase = (t_cur >> 3) * BM + wm * 64 + (lane >> 2);
            const int cbase = (t_cur & 7) * BN + wn * 32 + (lane & 3) * 2;
#pragma unroll
            for (int mt = 0; mt < 4; mt++) {
#pragma unroll
                for (int nt = 0; nt < 4; nt++) {
                    int col = cbase + nt * 8;
                    if (col < C_DIM) {
                        int row = rbase + mt * 16;
                        float* o0 = out + (size_t)row * C_DIM + col;
                        atomicAdd(o0,     (float)acc[mt][nt][0]);
                        atomicAdd(o0 + 1, (float)acc[mt][nt][1]);
                        float* o1 = out + (size_t)(row + 8) * C_DIM + col;
                        atomicAdd(o1,     (float)acc[mt][nt][2]);
                        atomicAdd(o1 + 1, (float)acc[mt][nt][3]);
                    }
                }
            }
#pragma unroll
            for (int a = 0; a < 4; a++)
#pragma unroll
                for (int b = 0; b < 4; b++)
#pragma unroll
                    for (int r = 0; r < 4; r++) acc[a][b][r] = 0;
            if (c_cur == CPT) { c_cur = 0; ++t_cur; }
        }
    }
}

// ============================================================================
// Host side
// ============================================================================
extern "C" void kernel_launch(void* const* d_in, const int* in_sizes, int n_in,
                              void* d_out, int out_size) {
    const float* inp = (const float*)d_in[0];   // [8192, 12288] fp32
    const float* wgt = (const float*)d_in[1];   // [1000, 12288] fp32
    float* out = (float*)d_out;                 // [8192, 1000] fp32

    // 1) fused sign-quantize to s8 (A + W)
    conv_kernel<<<(unsigned)(A_BLOCKS + W_BLOCKS), 256>>>(
        (const float4*)inp, (const float4*)wgt);

    // 2) zero output (atomic accumulation target; graph replays re-zero)
    cudaMemsetAsync(out, 0, (size_t)out_size * sizeof(float));

    // 3) int8 IMMA GEMM, balanced continuous-stream distribution
    static bool attr_set = false;
    if (!attr_set) {
        cudaFuncSetAttribute(bgemm_kernel,
                             cudaFuncAttributeMaxDynamicSharedMemorySize,
                             SMEM_BYTES);
        attr_set = true;
    }
    bgemm_kernel<<<NCTA, 256, SMEM_BYTES>>>(out);
}

// round 13
// speedup vs baseline: 2.3548x; 2.3548x over previous
#include <cuda_runtime.h>
#include <cstdint>

// ============================================================================
// Problem constants
// ============================================================================
#define K_DIM 12288
#define M_DIM 8192
#define C_DIM 1000
#define N_PAD 1024

// GEMM tiling (fp8 TN: A[M,K] row-major, B[N,K] row-major = "col" operand)
#define BM 128
#define BN 128
#define BK 128                      // bytes of K per chunk
#define CPT 96                      // chunks per tile (K_DIM / BK)
#define NTILES 512                  // (M/BM) * (N_PAD/BN) = 64*8
#define TOTAL_UNITS (NTILES * CPT)  // 49152 chunk-units
#define NCTA 296                    // 148 SMs * occ 2 -> single balanced wave
#define UNITS_BASE (TOTAL_UNITS / NCTA)               // 166
#define UNITS_REM  (TOTAL_UNITS - NCTA * UNITS_BASE)  // 16

#define STAGES 3
#define A_ST (BM * BK)              // 16384 B
#define B_ST (BN * BK)              // 16384 B
#define STG_BYTES (A_ST + B_ST)     // 32768 B
#define SMEM_BYTES (STAGES * STG_BYTES)  // 98304 B

// conv grid split
#define A_BLOCKS 24576              // (M*K/16)/256
#define W_BLOCKS 3072               // (N_PAD*K/16)/256

// e4m3 encodings of +1 / -1 (sign | exp=7(bias) | mantissa=0)
#define FP8_P1 0x38u
#define FP8_M1 0xB8u

// ============================================================================
// Device scratch (allocation-free: __device__ globals)
// ============================================================================
__device__ uint8_t g_A8[(size_t)M_DIM * K_DIM];   // sign(input)  as e4m3
__device__ uint8_t g_W8[(size_t)N_PAD * K_DIM];   // sign(weight) as e4m3, pad 0

// ============================================================================
// PTX helpers
// ============================================================================
__device__ __forceinline__ void cp16(uint32_t dst, const void* src) {
    asm volatile("cp.async.cg.shared.global [%0], [%1], 16;"
                 :: "r"(dst), "l"(src));
}
__device__ __forceinline__ void cp_commit() {
    asm volatile("cp.async.commit_group;");
}
__device__ __forceinline__ void cp_wait1() {
    asm volatile("cp.async.wait_group 1;");
}

__device__ __forceinline__ void ldsm_x4(uint32_t& r0, uint32_t& r1,
                                        uint32_t& r2, uint32_t& r3,
                                        uint32_t addr) {
    asm volatile("ldmatrix.sync.aligned.m8n8.x4.shared.b16 {%0,%1,%2,%3}, [%4];"
                 : "=r"(r0), "=r"(r1), "=r"(r2), "=r"(r3) : "r"(addr));
}

// FP8 e4m3 MMA, fp32 accumulate (exact for +-1 products, |sum| <= 12288)
__device__ __forceinline__ void qmma16832(float* c, const uint32_t* a,
                                          uint32_t b0, uint32_t b1) {
    asm volatile(
        "mma.sync.aligned.m16n8k32.row.col.f32.e4m3.e4m3.f32 "
        "{%0,%1,%2,%3}, {%4,%5,%6,%7}, {%8,%9}, {%0,%1,%2,%3};"
        : "+f"(c[0]), "+f"(c[1]), "+f"(c[2]), "+f"(c[3])
        : "r"(a[0]), "r"(a[1]), "r"(a[2]), "r"(a[3]), "r"(b0), "r"(b1));
}

__device__ __forceinline__ uint32_t sgnfp8(float x) {
    return (x > 0.f) ? FP8_P1 : ((x < 0.f) ? FP8_M1 : 0u);
}
__device__ __forceinline__ uint32_t pack4(float4 f) {
    return sgnfp8(f.x) | (sgnfp8(f.y) << 8) | (sgnfp8(f.z) << 16)
         | (sgnfp8(f.w) << 24);
}

// ============================================================================
// Kernel 1: fused sign-quantize fp32 -> e4m3 for A and W (16 elems/thread)
// ============================================================================
__global__ void conv_kernel(const float4* __restrict__ in,
                            const float4* __restrict__ w) {
    size_t b = blockIdx.x;
    if (b < A_BLOCKS) {
        size_t t = b * 256 + threadIdx.x;
        const float4* p = in + t * 4;
        uint4 o;
        o.x = pack4(p[0]); o.y = pack4(p[1]);
        o.z = pack4(p[2]); o.w = pack4(p[3]);
        reinterpret_cast<uint4*>(g_A8)[t] = o;
    } else {
        size_t t = (b - A_BLOCKS) * 256 + threadIdx.x;
        uint4 o = make_uint4(0u, 0u, 0u, 0u);
        if (t * 16 < (size_t)C_DIM * K_DIM) {   // rows >= 1000 stay zero
            const float4* p = w + t * 4;
            o.x = pack4(p[0]); o.y = pack4(p[1]);
            o.z = pack4(p[2]); o.w = pack4(p[3]);
        }
        reinterpret_cast<uint4*>(g_W8)[t] = o;
    }
}

// ============================================================================
// Kernel 2: fp8 QMMA GEMM, balanced continuous chunk stream.
// 296 CTAs each own a contiguous range of chunk-units (tile*96 + kchunk).
// cp.async pipeline runs continuously across tile boundaries; one
// __syncthreads per chunk; atomic fp32 epilogue per tile segment (exact).
// ============================================================================
__global__ void __launch_bounds__(256, 2)
bgemm_kernel(float* __restrict__ out) {
    extern __shared__ char smem[];
    const uint32_t sb = (uint32_t)__cvta_generic_to_shared(smem);

    const int tid = threadIdx.x;
    const int lane = tid & 31;
    const int wid = tid >> 5;
    const int wm = wid & 1;        // 2 warp rows   (64 m each)
    const int wn = wid >> 1;       // 4 warp cols   (32 n each)

    // ---- g2s copy offsets, base forms (j-th copy adds j*4096 / j*32*K_DIM) ----
    const uint32_t row0 = tid >> 3;
    const uint32_t col0 = (tid & 7u) * 16u;
    const uint32_t dst0 = row0 * BK + (col0 ^ ((row0 & 7u) * 16u));
    const uint32_t src0 = row0 * K_DIM + col0;

    // ---- ldmatrix address components ----
    const uint32_t lswz = (lane & 7u) * 16u;
    const uint32_t a_r0off = (uint32_t)(wm * 64 + (lane & 15)) * BK;
    const uint32_t axc = (((lane >> 4) & 1u) * 16u) ^ lswz;
    const uint32_t b_r0off =
        (uint32_t)(wn * 32 + ((lane >> 4) & 1) * 8 + (lane & 7)) * BK;
    const uint32_t bxc = (((lane >> 3) & 1u) * 16u) ^ lswz;

    // ---- balanced work range ----
    const int bid = blockIdx.x;
    const int u0 = bid * UNITS_BASE + min(bid, UNITS_REM);
    const int n_units = UNITS_BASE + (bid < UNITS_REM ? 1 : 0);

    // ---- stream cursors ----
    int t_cur = u0 / CPT;
    int c_cur = u0 - t_cur * CPT;

    float acc[4][4][4];
#pragma unroll
    for (int i = 0; i < 4; i++)
#pragma unroll
        for (int j = 0; j < 4; j++)
#pragma unroll
            for (int r = 0; r < 4; r++) acc[i][j][r] = 0.f;

    // ---- prologue: prefetch units u0, u0+1 into stages 0,1 ----
    int tp = t_cur, cp_ = c_cur;
#pragma unroll
    for (int s = 0; s < 2; s++) {
        uint32_t base = sb + s * STG_BYTES;
        uint32_t offA = (uint32_t)(tp >> 3) * (BM * K_DIM) + (uint32_t)cp_ * BK;
        uint32_t offW = (uint32_t)(tp & 7) * (BN * K_DIM) + (uint32_t)cp_ * BK;
#pragma unroll
        for (int j = 0; j < 4; j++)
            cp16(base + dst0 + j * 4096, g_A8 + offA + src0 + j * (32 * K_DIM));
#pragma unroll
        for (int j = 0; j < 4; j++)
            cp16(base + A_ST + dst0 + j * 4096,
                 g_W8 + offW + src0 + j * (32 * K_DIM));
        cp_commit();
        if (++cp_ == CPT) { cp_ = 0; ++tp; }
    }

    int st_cur = 0, st_pre = 2;

    for (int i = 0; i < n_units; i++) {
        cp_wait1();          // unit i's group arrived (<=1 pending: unit i+1)
        __syncthreads();     // collectivize; all threads done computing i-1

        // ---- prefetch unit u0+i+2 into stage st_pre ----
        if (i + 2 < n_units) {
            uint32_t base = sb + st_pre * STG_BYTES;
            uint32_t offA =
                (uint32_t)(tp >> 3) * (BM * K_DIM) + (uint32_t)cp_ * BK;
            uint32_t offW =
                (uint32_t)(tp & 7) * (BN * K_DIM) + (uint32_t)cp_ * BK;
#pragma unroll
            for (int j = 0; j < 4; j++)
                cp16(base + dst0 + j * 4096,
                     g_A8 + offA + src0 + j * (32 * K_DIM));
#pragma unroll
            for (int j = 0; j < 4; j++)
                cp16(base + A_ST + dst0 + j * 4096,
                     g_W8 + offW + src0 + j * (32 * K_DIM));
            if (++cp_ == CPT) { cp_ = 0; ++tp; }
        }
        cp_commit();
        if (++st_pre == STAGES) st_pre = 0;

        // ---- compute current chunk from stage st_cur ----
        {
            uint32_t sa = sb + st_cur * STG_BYTES;
            uint32_t sB = sa + A_ST;
#pragma unroll
            for (int ks = 0; ks < 4; ks++) {
                const uint32_t kc = ks * 32;
                uint32_t bf[4][2];
#pragma unroll
                for (int p = 0; p < 2; p++) {
                    uint32_t addr = sB + b_r0off + p * 2048 + (kc ^ bxc);
                    ldsm_x4(bf[2 * p][0], bf[2 * p][1],
                            bf[2 * p + 1][0], bf[2 * p + 1][1], addr);
                }
#pragma unroll
                for (int mt = 0; mt < 4; mt++) {
                    uint32_t af[4];
                    uint32_t addr = sa + a_r0off + mt * 2048 + (kc ^ axc);
                    ldsm_x4(af[0], af[1], af[2], af[3], addr);
#pragma unroll
                    for (int nt = 0; nt < 4; nt++)
                        qmma16832(acc[mt][nt], af, bf[nt][0], bf[nt][1]);
                }
            }
        }
        if (++st_cur == STAGES) st_cur = 0;

        // ---- advance & segment epilogue (overlaps in-flight cp.async) ----
        ++c_cur;
        if (c_cur == CPT || i == n_units - 1) {
            const int rbase = (t_cur >> 3) * BM + wm * 64 + (lane >> 2);
            const int cbase = (t_cur & 7) * BN + wn * 32 + (lane & 3) * 2;
#pragma unroll
            for (int mt = 0; mt < 4; mt++) {
#pragma unroll
                for (int nt = 0; nt < 4; nt++) {
                    int col = cbase + nt * 8;
                    if (col < C_DIM) {
                        int row = rbase + mt * 16;
                        float* o0 = out + (size_t)row * C_DIM + col;
                        atomicAdd(o0,     acc[mt][nt][0]);
                        atomicAdd(o0 + 1, acc[mt][nt][1]);
                        float* o1 = out + (size_t)(row + 8) * C_DIM + col;
                        atomicAdd(o1,     acc[mt][nt][2]);
                        atomicAdd(o1 + 1, acc[mt][nt][3]);
                    }
                }
            }
#pragma unroll
            for (int a = 0; a < 4; a++)
#pragma unroll
                for (int b = 0; b < 4; b++)
#pragma unroll
                    for (int r = 0; r < 4; r++) acc[a][b][r] = 0.f;
            if (c_cur == CPT) { c_cur = 0; ++t_cur; }
        }
    }
}

// ============================================================================
// Host side
// ============================================================================
extern "C" void kernel_launch(void* const* d_in, const int* in_sizes, int n_in,
                              void* d_out, int out_size) {
    const float* inp = (const float*)d_in[0];   // [8192, 12288] fp32
    const float* wgt = (const float*)d_in[1];   // [1000, 12288] fp32
    float* out = (float*)d_out;                 // [8192, 1000] fp32

    // 1) fused sign-quantize to e4m3 (A + W)
    conv_kernel<<<(unsigned)(A_BLOCKS + W_BLOCKS), 256>>>(
        (const float4*)inp, (const float4*)wgt);

    // 2) zero output (atomic accumulation target; graph replays re-zero)
    cudaMemsetAsync(out, 0, (size_t)out_size * sizeof(float));

    // 3) fp8 QMMA GEMM, balanced continuous-stream distribution
    static bool attr_set = false;
    if (!attr_set) {
        cudaFuncSetAttribute(bgemm_kernel,
                             cudaFuncAttributeMaxDynamicSharedMemorySize,
                             SMEM_BYTES);
        attr_set = true;
    }
    bgemm_kernel<<<NCTA, 256, SMEM_BYTES>>>(out);
}

// round 14
// speedup vs baseline: 2.4063x; 1.0219x over previous
#include <cuda_runtime.h>
#include <cuda_fp16.h>
#include <cstdint>

// ============================================================================
// Problem constants
// ============================================================================
#define K_DIM 12288
#define M_DIM 8192
#define C_DIM 1000
#define N_PAD 1024

// GEMM tiling (fp8 TN: A[M,K] row-major, B[N,K] row-major = "col" operand)
#define BM 128
#define BN 128
#define BK 128                      // bytes of K per chunk
#define CPT 96                      // chunks per tile (K_DIM / BK)
#define NTILES 512                  // (M/BM) * (N_PAD/BN) = 64*8
#define TOTAL_UNITS (NTILES * CPT)  // 49152 chunk-units
#define NCTA 296                    // 148 SMs * occ 2 -> single balanced wave
#define UNITS_BASE (TOTAL_UNITS / NCTA)               // 166
#define UNITS_REM  (TOTAL_UNITS - NCTA * UNITS_BASE)  // 16

#define DRAIN_CHUNKS 16             // 16*128 = 2048: f16-exact partial bound

#define STAGES 3
#define A_ST (BM * BK)              // 16384 B
#define B_ST (BN * BK)              // 16384 B
#define STG_BYTES (A_ST + B_ST)     // 32768 B
#define SMEM_BYTES (STAGES * STG_BYTES)  // 98304 B

// conv grid split
#define A_BLOCKS 24576              // (M*K/16)/256
#define W_BLOCKS 3072               // (N_PAD*K/16)/256

// e4m3 encodings of +1 / -1 (sign | exp=7(bias) | mantissa=0)
#define FP8_P1 0x38u
#define FP8_M1 0xB8u

// ============================================================================
// Device scratch (allocation-free: __device__ globals)
// ============================================================================
__device__ uint8_t g_A8[(size_t)M_DIM * K_DIM];   // sign(input)  as e4m3
__device__ uint8_t g_W8[(size_t)N_PAD * K_DIM];   // sign(weight) as e4m3, pad 0

// ============================================================================
// PTX helpers
// ============================================================================
__device__ __forceinline__ void cp16(uint32_t dst, const void* src) {
    asm volatile("cp.async.cg.shared.global [%0], [%1], 16;"
                 :: "r"(dst), "l"(src));
}
__device__ __forceinline__ void cp_commit() {
    asm volatile("cp.async.commit_group;");
}
__device__ __forceinline__ void cp_wait1() {
    asm volatile("cp.async.wait_group 1;");
}

__device__ __forceinline__ void ldsm_x4(uint32_t& r0, uint32_t& r1,
                                        uint32_t& r2, uint32_t& r3,
                                        uint32_t addr) {
    asm volatile("ldmatrix.sync.aligned.m8n8.x4.shared.b16 {%0,%1,%2,%3}, [%4];"
                 : "=r"(r0), "=r"(r1), "=r"(r2), "=r"(r3) : "r"(addr));
}

// FP8 e4m3 MMA, f16 accumulate (exact while |acc| <= 2048; drained every
// DRAIN_CHUNKS chunks). C/D fragment = 2 regs of f16x2.
__device__ __forceinline__ void qmma16832_f16(uint32_t* c, const uint32_t* a,
                                              uint32_t b0, uint32_t b1) {
    asm volatile(
        "mma.sync.aligned.m16n8k32.row.col.f16.e4m3.e4m3.f16 "
        "{%0,%1}, {%2,%3,%4,%5}, {%6,%7}, {%0,%1};"
        : "+r"(c[0]), "+r"(c[1])
        : "r"(a[0]), "r"(a[1]), "r"(a[2]), "r"(a[3]), "r"(b0), "r"(b1));
}

__device__ __forceinline__ uint32_t sgnfp8(float x) {
    return (x > 0.f) ? FP8_P1 : ((x < 0.f) ? FP8_M1 : 0u);
}
__device__ __forceinline__ uint32_t pack4(float4 f) {
    return sgnfp8(f.x) | (sgnfp8(f.y) << 8) | (sgnfp8(f.z) << 16)
         | (sgnfp8(f.w) << 24);
}

// ============================================================================
// Kernel 1: fused sign-quantize fp32 -> e4m3 for A and W (16 elems/thread)
// ============================================================================
__global__ void conv_kernel(const float4* __restrict__ in,
                            const float4* __restrict__ w) {
    size_t b = blockIdx.x;
    if (b < A_BLOCKS) {
        size_t t = b * 256 + threadIdx.x;
        const float4* p = in + t * 4;
        uint4 o;
        o.x = pack4(p[0]); o.y = pack4(p[1]);
        o.z = pack4(p[2]); o.w = pack4(p[3]);
        reinterpret_cast<uint4*>(g_A8)[t] = o;
    } else {
        size_t t = (b - A_BLOCKS) * 256 + threadIdx.x;
        uint4 o = make_uint4(0u, 0u, 0u, 0u);
        if (t * 16 < (size_t)C_DIM * K_DIM) {   // rows >= 1000 stay zero
            const float4* p = w + t * 4;
            o.x = pack4(p[0]); o.y = pack4(p[1]);
            o.z = pack4(p[2]); o.w = pack4(p[3]);
        }
        reinterpret_cast<uint4*>(g_W8)[t] = o;
    }
}

// ============================================================================
// Kernel 2: fp8 QMMA (f16 accum) GEMM, balanced continuous chunk stream.
// 296 CTAs each own a contiguous range of chunk-units (tile*96 + kchunk).
// Fragment loads batched per k-step; accumulators drained to fp32 gmem via
// atomicAdd every <=16 chunks (exact: |partial| <= 2048, integers).
// ============================================================================
__global__ void __launch_bounds__(256, 2)
bgemm_kernel(float* __restrict__ out) {
    extern __shared__ char smem[];
    const uint32_t sb = (uint32_t)__cvta_generic_to_shared(smem);

    const int tid = threadIdx.x;
    const int lane = tid & 31;
    const int wid = tid >> 5;
    const int wm = wid & 1;        // 2 warp rows   (64 m each)
    const int wn = wid >> 1;       // 4 warp cols   (32 n each)

    // ---- g2s copy offsets, base forms (j-th copy adds j*4096 / j*32*K_DIM) ----
    const uint32_t row0 = tid >> 3;
    const uint32_t col0 = (tid & 7u) * 16u;
    const uint32_t dst0 = row0 * BK + (col0 ^ ((row0 & 7u) * 16u));
    const uint32_t src0 = row0 * K_DIM + col0;

    // ---- ldmatrix address components ----
    const uint32_t lswz = (lane & 7u) * 16u;
    const uint32_t a_r0off = (uint32_t)(wm * 64 + (lane & 15)) * BK;
    const uint32_t axc = (((lane >> 4) & 1u) * 16u) ^ lswz;
    const uint32_t b_r0off =
        (uint32_t)(wn * 32 + ((lane >> 4) & 1) * 8 + (lane & 7)) * BK;
    const uint32_t bxc = (((lane >> 3) & 1u) * 16u) ^ lswz;

    // ---- balanced work range ----
    const int bid = blockIdx.x;
    const int u0 = bid * UNITS_BASE + min(bid, UNITS_REM);
    const int n_units = UNITS_BASE + (bid < UNITS_REM ? 1 : 0);

    // ---- stream cursors ----
    int t_cur = u0 / CPT;
    int c_cur = u0 - t_cur * CPT;

    uint32_t acc[4][4][2];         // f16x2 accumulators
#pragma unroll
    for (int i = 0; i < 4; i++)
#pragma unroll
        for (int j = 0; j < 4; j++) { acc[i][j][0] = 0u; acc[i][j][1] = 0u; }

    // ---- prologue: prefetch units u0, u0+1 into stages 0,1 ----
    int tp = t_cur, cp_ = c_cur;
#pragma unroll
    for (int s = 0; s < 2; s++) {
        uint32_t base = sb + s * STG_BYTES;
        uint32_t offA = (uint32_t)(tp >> 3) * (BM * K_DIM) + (uint32_t)cp_ * BK;
        uint32_t offW = (uint32_t)(tp & 7) * (BN * K_DIM) + (uint32_t)cp_ * BK;
#pragma unroll
        for (int j = 0; j < 4; j++)
            cp16(base + dst0 + j * 4096, g_A8 + offA + src0 + j * (32 * K_DIM));
#pragma unroll
        for (int j = 0; j < 4; j++)
            cp16(base + A_ST + dst0 + j * 4096,
                 g_W8 + offW + src0 + j * (32 * K_DIM));
        cp_commit();
        if (++cp_ == CPT) { cp_ = 0; ++tp; }
    }

    int st_cur = 0, st_pre = 2;
    int cnt = 0;   // chunks since last drain

    for (int i = 0; i < n_units; i++) {
        cp_wait1();          // unit i's group arrived (<=1 pending: unit i+1)
        __syncthreads();     // collectivize; all threads done computing i-1

        // ---- prefetch unit u0+i+2 into stage st_pre ----
        if (i + 2 < n_units) {
            uint32_t base = sb + st_pre * STG_BYTES;
            uint32_t offA =
                (uint32_t)(tp >> 3) * (BM * K_DIM) + (uint32_t)cp_ * BK;
            uint32_t offW =
                (uint32_t)(tp & 7) * (BN * K_DIM) + (uint32_t)cp_ * BK;
#pragma unroll
            for (int j = 0; j < 4; j++)
                cp16(base + dst0 + j * 4096,
                     g_A8 + offA + src0 + j * (32 * K_DIM));
#pragma unroll
            for (int j = 0; j < 4; j++)
                cp16(base + A_ST + dst0 + j * 4096,
                     g_W8 + offW + src0 + j * (32 * K_DIM));
            if (++cp_ == CPT) { cp_ = 0; ++tp; }
        }
        cp_commit();
        if (++st_pre == STAGES) st_pre = 0;

        // ---- compute current chunk from stage st_cur ----
        {
            uint32_t sa = sb + st_cur * STG_BYTES;
            uint32_t sB = sa + A_ST;
#pragma unroll
            for (int ks = 0; ks < 4; ks++) {
                const uint32_t kc = ks * 32;
                // batch ALL fragment loads for this k-step (6 ldsm)
                uint32_t bf[4][2];
                uint32_t af[4][4];
#pragma unroll
                for (int p = 0; p < 2; p++) {
                    uint32_t addr = sB + b_r0off + p * 2048 + (kc ^ bxc);
                    ldsm_x4(bf[2 * p][0], bf[2 * p][1],
                            bf[2 * p + 1][0], bf[2 * p + 1][1], addr);
                }
#pragma unroll
                for (int mt = 0; mt < 4; mt++) {
                    uint32_t addr = sa + a_r0off + mt * 2048 + (kc ^ axc);
                    ldsm_x4(af[mt][0], af[mt][1], af[mt][2], af[mt][3], addr);
                }
                // 16 QMMAs
#pragma unroll
                for (int mt = 0; mt < 4; mt++)
#pragma unroll
                    for (int nt = 0; nt < 4; nt++)
                        qmma16832_f16(acc[mt][nt], af[mt],
                                      bf[nt][0], bf[nt][1]);
            }
        }
        if (++st_cur == STAGES) st_cur = 0;

        // ---- advance & drain (every <=16 chunks, tile end, segment end) ----
        ++c_cur;
        ++cnt;
        if (cnt == DRAIN_CHUNKS || c_cur == CPT || i == n_units - 1) {
            const int rbase = (t_cur >> 3) * BM + wm * 64 + (lane >> 2);
            const int cbase = (t_cur & 7) * BN + wn * 32 + (lane & 3) * 2;
#pragma unroll
            for (int mt = 0; mt < 4; mt++) {
#pragma unroll
                for (int nt = 0; nt < 4; nt++) {
                    int col = cbase + nt * 8;
                    if (col < C_DIM) {
                        int row = rbase + mt * 16;
                        float2 v0 = __half22float2(
                            *reinterpret_cast<__half2*>(&acc[mt][nt][0]));
                        float2 v1 = __half22float2(
                            *reinterpret_cast<__half2*>(&acc[mt][nt][1]));
                        float* o0 = out + (size_t)row * C_DIM + col;
                        atomicAdd(o0,     v0.x);
                        atomicAdd(o0 + 1, v0.y);
                        float* o1 = out + (size_t)(row + 8) * C_DIM + col;
                        atomicAdd(o1,     v1.x);
                        atomicAdd(o1 + 1, v1.y);
                    }
                }
            }
#pragma unroll
            for (int a = 0; a < 4; a++)
#pragma unroll
                for (int b = 0; b < 4; b++) {
                    acc[a][b][0] = 0u; acc[a][b][1] = 0u;
                }
            cnt = 0;
            if (c_cur == CPT) { c_cur = 0; ++t_cur; }
        }
    }
}

// ============================================================================
// Host side
// ============================================================================
extern "C" void kernel_launch(void* const* d_in, const int* in_sizes, int n_in,
                              void* d_out, int out_size) {
    const float* inp = (const float*)d_in[0];   // [8192, 12288] fp32
    const float* wgt = (const float*)d_in[1];   // [1000, 12288] fp32
    float* out = (float*)d_out;                 // [8192, 1000] fp32

    // 1) fused sign-quantize to e4m3 (A + W)
    conv_kernel<<<(unsigned)(A_BLOCKS + W_BLOCKS), 256>>>(
        (const float4*)inp, (const float4*)wgt);

    // 2) zero output (atomic accumulation target; graph replays re-zero)
    cudaMemsetAsync(out, 0, (size_t)out_size * sizeof(float));

    // 3) fp8 QMMA (f16 accum) GEMM, balanced continuous-stream distribution
    static bool attr_set = false;
    if (!attr_set) {
        cudaFuncSetAttribute(bgemm_kernel,
                             cudaFuncAttributeMaxDynamicSharedMemorySize,
                             SMEM_BYTES);
        attr_set = true;
    }
    bgemm_kernel<<<NCTA, 256, SMEM_BYTES>>>(out);
}